// round 10
// baseline (speedup 1.0000x reference)
#include <cuda_runtime.h>

#define NEG_SLOPE 0.2f

// x: [B=8, C=256, H=128, W=128] f32. row = b*C+c. group g == batch b.
static constexpr int NROWS = 2048;
static constexpr int ROW_ELEMS = 16384;           // H*W
static constexpr int ROW_VEC4 = ROW_ELEMS / 4;    // 4096
static constexpr int C = 256;
static constexpr int CS = 16;
static constexpr int NGROUPS = 8;                 // == B
static constexpr int GROUP_ROWS = 256;            // == C

static constexpr int GRID = 1024;                 // single co-resident wave
static constexpr int QUARTER_VEC4 = ROW_VEC4 / 4; // 1024 float4 = 16KB

__device__ float g_sum[NROWS];                    // row sums (atomic accum), zero-init
__device__ unsigned int g_cnt[NGROUPS];           // per-group arrival counters
__device__ unsigned int g_fin;                    // completion counter

struct f8 { float a0,a1,a2,a3,a4,a5,a6,a7; };

__device__ __forceinline__ f8 ldg_evict_last_32B(const void* p) {
    unsigned long long d0, d1, d2, d3;
    asm("ld.global.L2::evict_last.v4.b64 {%0,%1,%2,%3}, [%4];"
        : "=l"(d0), "=l"(d1), "=l"(d2), "=l"(d3) : "l"(p));
    f8 r;
    r.a0 = __uint_as_float((unsigned)(d0)); r.a1 = __uint_as_float((unsigned)(d0 >> 32));
    r.a2 = __uint_as_float((unsigned)(d1)); r.a3 = __uint_as_float((unsigned)(d1 >> 32));
    r.a4 = __uint_as_float((unsigned)(d2)); r.a5 = __uint_as_float((unsigned)(d2 >> 32));
    r.a6 = __uint_as_float((unsigned)(d3)); r.a7 = __uint_as_float((unsigned)(d3 >> 32));
    return r;
}

__global__ __launch_bounds__(256, 8)
void se_pipe_kernel(const float* __restrict__ x,
                    const float* __restrict__ w1,
                    const float* __restrict__ b1,
                    const float* __restrict__ w2,
                    const float* __restrict__ b2,
                    float* __restrict__ out) {
    const int tid = threadIdx.x;
    const int cta = blockIdx.x;
    const int row_in_group = cta >> 2;   // 0..255 (== channel c)
    const int quarter = cta & 3;

    __shared__ float warp_sums[8];
    __shared__ float sh_y1[CS];
    __shared__ float sh_gate;
    __shared__ bool sh_last;

    // ---- per-round lambdas (inlined manually) ----
    for (int g = 0; g < NGROUPS; g++) {
        // ================= POOL my quarter of group g =================
        {
            const int row = g * GROUP_ROWS + row_in_group;
            const char* __restrict__ xq = reinterpret_cast<const char*>(x)
                + ((size_t)row * ROW_VEC4 + (size_t)quarter * QUARTER_VEC4) * 16;
            float s = 0.f;
#pragma unroll
            for (int i = 0; i < QUARTER_VEC4 / 2 / 256; i++) {  // 2 iters of 32B
                f8 v = ldg_evict_last_32B(xq + (size_t)(tid + i * 256) * 32);
                s += ((v.a0 + v.a1) + (v.a2 + v.a3)) + ((v.a4 + v.a5) + (v.a6 + v.a7));
            }
#pragma unroll
            for (int off = 16; off > 0; off >>= 1)
                s += __shfl_xor_sync(0xFFFFFFFF, s, off);
            if ((tid & 31) == 0) warp_sums[tid >> 5] = s;
            __syncthreads();
            if (tid == 0) {
                float tot = 0.f;
#pragma unroll
                for (int w = 0; w < 8; w++) tot += warp_sums[w];
                atomicAdd(&g_sum[row], tot);
                __threadfence();
                atomicAdd(&g_cnt[g], 1u);
            }
            __syncthreads();
        }

        // ================= SCALE my quarter of group g-1 =================
        if (g >= 1) {
            const int gg = g - 1;
            if (tid == 0) {
                while (atomicAdd(&g_cnt[gg], 0u) < (unsigned)GRID) __nanosleep(64);
            }
            __syncthreads();

            const int b = gg;
            const int c = row_in_group;
            // inline FC (redundant per CTA): y1 = leaky(w1·mean + b1); gate = sig(w2[c]·y1 + b2[c])
            {
                const int s_idx = tid >> 4;
                const int cc = tid & 15;
                const float* __restrict__ wrow = w1 + s_idx * C;
                float part = 0.f;
#pragma unroll
                for (int k = 0; k < C / 16; k++) {
                    const int cidx = cc + k * 16;
                    part += wrow[cidx] * (__ldcg(&g_sum[b * C + cidx]) * (1.0f / ROW_ELEMS));
                }
#pragma unroll
                for (int off = 8; off > 0; off >>= 1)
                    part += __shfl_down_sync(0xFFFFFFFF, part, off, 16);
                if (cc == 0) {
                    part += b1[s_idx];
                    sh_y1[s_idx] = (part >= 0.f) ? part : NEG_SLOPE * part;
                }
            }
            __syncthreads();
            if (tid == 0) {
                const float* __restrict__ w2row = w2 + c * CS;
                float acc = b2[c];
#pragma unroll
                for (int s = 0; s < CS; s++) acc += w2row[s] * sh_y1[s];
                sh_gate = 1.0f / (1.0f + __expf(-acc));
            }
            __syncthreads();
            const float gt = sh_gate;

            const int row = gg * GROUP_ROWS + row_in_group;
            const size_t base = (size_t)row * ROW_VEC4 + (size_t)quarter * QUARTER_VEC4;
            const float4* __restrict__ xr = reinterpret_cast<const float4*>(x) + base;
            float4* __restrict__ orow = reinterpret_cast<float4*>(out) + base;
#pragma unroll
            for (int i = 0; i < QUARTER_VEC4 / 256; i++) {  // 4 iters
                float4 v = xr[tid + i * 256];   // L2 hit: pooled one round ago, evict_last
                v.x *= gt; v.y *= gt; v.z *= gt; v.w *= gt;
                orow[tid + i * 256] = v;
            }
            __syncthreads();
        }
    }

    // ================= epilogue: scale last group =================
    {
        const int gg = NGROUPS - 1;
        if (tid == 0) {
            while (atomicAdd(&g_cnt[gg], 0u) < (unsigned)GRID) __nanosleep(64);
        }
        __syncthreads();

        const int b = gg;
        const int c = row_in_group;
        {
            const int s_idx = tid >> 4;
            const int cc = tid & 15;
            const float* __restrict__ wrow = w1 + s_idx * C;
            float part = 0.f;
#pragma unroll
            for (int k = 0; k < C / 16; k++) {
                const int cidx = cc + k * 16;
                part += wrow[cidx] * (__ldcg(&g_sum[b * C + cidx]) * (1.0f / ROW_ELEMS));
            }
#pragma unroll
            for (int off = 8; off > 0; off >>= 1)
                part += __shfl_down_sync(0xFFFFFFFF, part, off, 16);
            if (cc == 0) {
                part += b1[s_idx];
                sh_y1[s_idx] = (part >= 0.f) ? part : NEG_SLOPE * part;
            }
        }
        __syncthreads();
        if (tid == 0) {
            const float* __restrict__ w2row = w2 + c * CS;
            float acc = b2[c];
#pragma unroll
            for (int s = 0; s < CS; s++) acc += w2row[s] * sh_y1[s];
            sh_gate = 1.0f / (1.0f + __expf(-acc));
        }
        __syncthreads();
        const float gt = sh_gate;

        const int row = gg * GROUP_ROWS + row_in_group;
        const size_t base = (size_t)row * ROW_VEC4 + (size_t)quarter * QUARTER_VEC4;
        const float4* __restrict__ xr = reinterpret_cast<const float4*>(x) + base;
        float4* __restrict__ orow = reinterpret_cast<float4*>(out) + base;
#pragma unroll
        for (int i = 0; i < QUARTER_VEC4 / 256; i++) {
            float4 v = xr[tid + i * 256];
            v.x *= gt; v.y *= gt; v.z *= gt; v.w *= gt;
            orow[tid + i * 256] = v;
        }
    }

    // ================= replay-safe reset by the last CTA =================
    if (tid == 0) {
        unsigned int prev = atomicAdd(&g_fin, 1u);
        sh_last = (prev == GRID - 1);
    }
    __syncthreads();
    if (sh_last) {
        for (int i = tid; i < NROWS; i += 256) g_sum[i] = 0.f;
        if (tid < NGROUPS) g_cnt[tid] = 0u;
        __syncthreads();
        if (tid == 0) {
            __threadfence();
            g_fin = 0u;
        }
    }
}

extern "C" void kernel_launch(void* const* d_in, const int* in_sizes, int n_in,
                              void* d_out, int out_size) {
    const float* x  = (const float*)d_in[0];
    const float* w1 = (const float*)d_in[1];
    const float* b1 = (const float*)d_in[2];
    const float* w2 = (const float*)d_in[3];
    const float* b2 = (const float*)d_in[4];
    float* out = (float*)d_out;

    se_pipe_kernel<<<GRID, 256>>>(x, w1, b1, w2, b2, out);
}

// round 11
// speedup vs baseline: 1.9511x; 1.9511x over previous
#include <cuda_runtime.h>

#define NEG_SLOPE 0.2f

// x: [B=8, C=256, H=128, W=128] f32. row = b*C+c.
static constexpr int NROWS = 2048;
static constexpr int ROW_ELEMS = 16384;          // H*W
static constexpr int ROW_VEC4 = ROW_ELEMS / 4;   // 4096
static constexpr int C = 256;
static constexpr int CS = 16;

static constexpr int GROUP_ROWS = 512;             // 2 batches = 33.5 MB
static constexpr int NGROUPS = NROWS / GROUP_ROWS; // 4

static constexpr int SCALE_CTAS = 2 * GROUP_ROWS;  // 1024: two CTAs per scale row
static constexpr int GAP_CTAS = GROUP_ROWS;        // 512
static constexpr int GRID = SCALE_CTAS + GAP_CTAS; // 1536

__device__ float g_y[NROWS];   // pooled means

struct f8 { float a0,a1,a2,a3,a4,a5,a6,a7; };

// 32B load, L2 evict_last: pin the freshly-pooled group until next step's scale.
__device__ __forceinline__ f8 ldg_evict_last_32B(const void* p) {
    unsigned long long d0, d1, d2, d3;
    asm("ld.global.L2::evict_last.v4.b64 {%0,%1,%2,%3}, [%4];"
        : "=l"(d0), "=l"(d1), "=l"(d2), "=l"(d3) : "l"(p));
    f8 r;
    r.a0 = __uint_as_float((unsigned)(d0)); r.a1 = __uint_as_float((unsigned)(d0 >> 32));
    r.a2 = __uint_as_float((unsigned)(d1)); r.a3 = __uint_as_float((unsigned)(d1 >> 32));
    r.a4 = __uint_as_float((unsigned)(d2)); r.a5 = __uint_as_float((unsigned)(d2 >> 32));
    r.a6 = __uint_as_float((unsigned)(d3)); r.a7 = __uint_as_float((unsigned)(d3 >> 32));
    return r;
}

// plain 32B load (scale's re-read: wants the L2 hit, no policy change)
__device__ __forceinline__ f8 ldg_32B(const void* p) {
    unsigned long long d0, d1, d2, d3;
    asm("ld.global.v4.b64 {%0,%1,%2,%3}, [%4];"
        : "=l"(d0), "=l"(d1), "=l"(d2), "=l"(d3) : "l"(p));
    f8 r;
    r.a0 = __uint_as_float((unsigned)(d0)); r.a1 = __uint_as_float((unsigned)(d0 >> 32));
    r.a2 = __uint_as_float((unsigned)(d1)); r.a3 = __uint_as_float((unsigned)(d1 >> 32));
    r.a4 = __uint_as_float((unsigned)(d2)); r.a5 = __uint_as_float((unsigned)(d2 >> 32));
    r.a6 = __uint_as_float((unsigned)(d3)); r.a7 = __uint_as_float((unsigned)(d3 >> 32));
    return r;
}

// 32B store, L2 evict_first: out is write-once, keep it from evicting pinned x.
__device__ __forceinline__ void stg_evict_first_32B(void* p, const f8& v) {
    unsigned long long d0 = ((unsigned long long)__float_as_uint(v.a1) << 32) | __float_as_uint(v.a0);
    unsigned long long d1 = ((unsigned long long)__float_as_uint(v.a3) << 32) | __float_as_uint(v.a2);
    unsigned long long d2 = ((unsigned long long)__float_as_uint(v.a5) << 32) | __float_as_uint(v.a4);
    unsigned long long d3 = ((unsigned long long)__float_as_uint(v.a7) << 32) | __float_as_uint(v.a6);
    asm volatile("st.global.L2::evict_first.v4.b64 [%0], {%1,%2,%3,%4};"
                 :: "l"(p), "l"(d0), "l"(d1), "l"(d2), "l"(d3) : "memory");
}

// ---------------------------------------------------------------------------
// Pipelined step kernel (R8 structure, byte-balanced ~64KB/CTA):
//   bid in [0, 1024):    scale HALF-row of group (step-1)
//   bid in [1024, 1536): gap one row of group step (evict_last install)
// ---------------------------------------------------------------------------
__global__ __launch_bounds__(256) void pipe_kernel(const float* __restrict__ x,
                                                   const float* __restrict__ w1,
                                                   const float* __restrict__ b1,
                                                   const float* __restrict__ w2,
                                                   const float* __restrict__ b2,
                                                   float* __restrict__ out,
                                                   int step) {
    const int tid = threadIdx.x;
    const int bid = blockIdx.x;

    if (bid >= SCALE_CTAS) {
        // ---------------- GAP role: pool one row of group `step` ----------------
        if (step >= NGROUPS) return;
        const int row = step * GROUP_ROWS + (bid - SCALE_CTAS);
        const char* __restrict__ xr =
            reinterpret_cast<const char*>(x) + (size_t)row * (size_t)ROW_ELEMS * 4;

        float s = 0.f;
#pragma unroll
        for (int i = 0; i < ROW_ELEMS / 8 / 256; i++) {   // 8 iters of 32B
            f8 v = ldg_evict_last_32B(xr + (size_t)(tid + i * 256) * 32);
            s += ((v.a0 + v.a1) + (v.a2 + v.a3)) + ((v.a4 + v.a5) + (v.a6 + v.a7));
        }
#pragma unroll
        for (int off = 16; off > 0; off >>= 1)
            s += __shfl_xor_sync(0xFFFFFFFF, s, off);

        __shared__ float warp_sums[8];
        if ((tid & 31) == 0) warp_sums[tid >> 5] = s;
        __syncthreads();
        if (tid == 0) {
            float tot = 0.f;
#pragma unroll
            for (int w = 0; w < 8; w++) tot += warp_sums[w];
            g_y[row] = tot * (1.0f / ROW_ELEMS);
        }
        return;
    }

    // ------------- SCALE role: gate + scale half a row of group `step-1` -------------
    if (step < 1) return;
    const int row = (step - 1) * GROUP_ROWS + (bid >> 1);
    const int half = bid & 1;
    const int b = row / C;
    const int c = row % C;

    // Inline FC (redundant per CTA; FMA pipe otherwise idle):
    __shared__ float sh_y1[CS];
    __shared__ float sh_gate;
    {
        const int s_idx = tid >> 4;   // 0..15
        const int cc = tid & 15;      // 0..15
        const float* __restrict__ yb = g_y + b * C;
        const float* __restrict__ wrow = w1 + s_idx * C;
        float part = 0.f;
#pragma unroll
        for (int k = 0; k < C / 16; k++) {
            const int cidx = cc + k * 16;
            part += wrow[cidx] * yb[cidx];
        }
#pragma unroll
        for (int off = 8; off > 0; off >>= 1)
            part += __shfl_down_sync(0xFFFFFFFF, part, off, 16);
        if (cc == 0) {
            part += b1[s_idx];
            sh_y1[s_idx] = (part >= 0.f) ? part : NEG_SLOPE * part;
        }
    }
    __syncthreads();
    if (tid == 0) {
        const float* __restrict__ w2row = w2 + c * CS;
        float acc = b2[c];
#pragma unroll
        for (int s = 0; s < CS; s++) acc += w2row[s] * sh_y1[s];
        sh_gate = 1.0f / (1.0f + __expf(-acc));
    }
    __syncthreads();
    const float g = sh_gate;

    // half-row = 8192 floats = 1024 x 32B chunks; 256 threads -> 4 iters
    const size_t base_bytes =
        ((size_t)row * ROW_ELEMS + (size_t)half * (ROW_ELEMS / 2)) * 4;
    const char* __restrict__ xr = reinterpret_cast<const char*>(x) + base_bytes;
    char* __restrict__ orow = reinterpret_cast<char*>(out) + base_bytes;
#pragma unroll
    for (int i = 0; i < ROW_ELEMS / 2 / 8 / 256; i++) {   // 4 iters
        const size_t off = (size_t)(tid + i * 256) * 32;
        f8 v = ldg_32B(xr + off);   // mostly L2 hit: pinned by previous step's gap
        v.a0 *= g; v.a1 *= g; v.a2 *= g; v.a3 *= g;
        v.a4 *= g; v.a5 *= g; v.a6 *= g; v.a7 *= g;
        stg_evict_first_32B(orow + off, v);
    }
}

extern "C" void kernel_launch(void* const* d_in, const int* in_sizes, int n_in,
                              void* d_out, int out_size) {
    const float* x  = (const float*)d_in[0];
    const float* w1 = (const float*)d_in[1];
    const float* b1 = (const float*)d_in[2];
    const float* w2 = (const float*)d_in[3];
    const float* b2 = (const float*)d_in[4];
    float* out = (float*)d_out;

    // steps: 0 = gap(g0); 1..3 = scale(g-1)+gap(g); 4 = scale(g3)
    for (int step = 0; step <= NGROUPS; step++) {
        pipe_kernel<<<GRID, 256>>>(x, w1, b1, w2, b2, out, step);
    }
}

// round 12
// speedup vs baseline: 2.0882x; 1.0703x over previous
#include <cuda_runtime.h>

#define NEG_SLOPE 0.2f

// x: [B=8, C=256, H=128, W=128] f32. row = b*C+c.
static constexpr int NROWS = 2048;
static constexpr int ROW_ELEMS = 16384;          // H*W
static constexpr int C = 256;
static constexpr int CS = 16;

static constexpr int GROUP_ROWS = 512;             // 2 batches = 33.5 MB
static constexpr int NGROUPS = NROWS / GROUP_ROWS; // 4

static constexpr int SCALE_CTAS = 2 * GROUP_ROWS;  // 1024: two CTAs per scale row
static constexpr int GAP_CTAS = GROUP_ROWS;        // 512
static constexpr int GRID = SCALE_CTAS + GAP_CTAS; // 1536

__device__ float g_y[NROWS];   // pooled means

struct f8 { float a0,a1,a2,a3,a4,a5,a6,a7; };

__device__ __forceinline__ f8 ldg_evict_last_32B(const void* p) {
    unsigned long long d0, d1, d2, d3;
    asm("ld.global.L2::evict_last.v4.b64 {%0,%1,%2,%3}, [%4];"
        : "=l"(d0), "=l"(d1), "=l"(d2), "=l"(d3) : "l"(p));
    f8 r;
    r.a0 = __uint_as_float((unsigned)(d0)); r.a1 = __uint_as_float((unsigned)(d0 >> 32));
    r.a2 = __uint_as_float((unsigned)(d1)); r.a3 = __uint_as_float((unsigned)(d1 >> 32));
    r.a4 = __uint_as_float((unsigned)(d2)); r.a5 = __uint_as_float((unsigned)(d2 >> 32));
    r.a6 = __uint_as_float((unsigned)(d3)); r.a7 = __uint_as_float((unsigned)(d3 >> 32));
    return r;
}

__device__ __forceinline__ f8 ldg_32B(const void* p) {
    unsigned long long d0, d1, d2, d3;
    asm("ld.global.v4.b64 {%0,%1,%2,%3}, [%4];"
        : "=l"(d0), "=l"(d1), "=l"(d2), "=l"(d3) : "l"(p));
    f8 r;
    r.a0 = __uint_as_float((unsigned)(d0)); r.a1 = __uint_as_float((unsigned)(d0 >> 32));
    r.a2 = __uint_as_float((unsigned)(d1)); r.a3 = __uint_as_float((unsigned)(d1 >> 32));
    r.a4 = __uint_as_float((unsigned)(d2)); r.a5 = __uint_as_float((unsigned)(d2 >> 32));
    r.a6 = __uint_as_float((unsigned)(d3)); r.a7 = __uint_as_float((unsigned)(d3 >> 32));
    return r;
}

__device__ __forceinline__ void stg_evict_first_32B(void* p, const f8& v) {
    unsigned long long d0 = ((unsigned long long)__float_as_uint(v.a1) << 32) | __float_as_uint(v.a0);
    unsigned long long d1 = ((unsigned long long)__float_as_uint(v.a3) << 32) | __float_as_uint(v.a2);
    unsigned long long d2 = ((unsigned long long)__float_as_uint(v.a5) << 32) | __float_as_uint(v.a4);
    unsigned long long d3 = ((unsigned long long)__float_as_uint(v.a7) << 32) | __float_as_uint(v.a6);
    asm volatile("st.global.L2::evict_first.v4.b64 [%0], {%1,%2,%3,%4};"
                 :: "l"(p), "l"(d0), "l"(d1), "l"(d2), "l"(d3) : "memory");
}

// ---------------------------------------------------------------------------
// Pipelined step kernel with PDL:
//   - every CTA signals launch_dependents at entry (next step may begin
//     placing CTAs as this step's CTAs retire -> boundary bubbles overlap)
//   - only the scale role waits (it reads g_y produced by the previous step);
//     the gap role has no cross-step dependency and streams immediately.
//   bid in [0, 1024):    scale HALF-row of group (step-1)
//   bid in [1024, 1536): gap one row of group step (evict_last install)
// ---------------------------------------------------------------------------
__global__ __launch_bounds__(256) void pipe_kernel(const float* __restrict__ x,
                                                   const float* __restrict__ w1,
                                                   const float* __restrict__ b1,
                                                   const float* __restrict__ w2,
                                                   const float* __restrict__ b2,
                                                   float* __restrict__ out,
                                                   int step) {
    // allow the next step's grid to launch as SM slots free up
    asm volatile("griddepcontrol.launch_dependents;");

    const int tid = threadIdx.x;
    const int bid = blockIdx.x;

    if (bid >= SCALE_CTAS) {
        // ---------------- GAP role: pool one row of group `step` ----------------
        if (step >= NGROUPS) return;
        const int row = step * GROUP_ROWS + (bid - SCALE_CTAS);
        const char* __restrict__ xr =
            reinterpret_cast<const char*>(x) + (size_t)row * (size_t)ROW_ELEMS * 4;

        float s = 0.f;
#pragma unroll
        for (int i = 0; i < ROW_ELEMS / 8 / 256; i++) {   // 8 iters of 32B
            f8 v = ldg_evict_last_32B(xr + (size_t)(tid + i * 256) * 32);
            s += ((v.a0 + v.a1) + (v.a2 + v.a3)) + ((v.a4 + v.a5) + (v.a6 + v.a7));
        }
#pragma unroll
        for (int off = 16; off > 0; off >>= 1)
            s += __shfl_xor_sync(0xFFFFFFFF, s, off);

        __shared__ float warp_sums[8];
        if ((tid & 31) == 0) warp_sums[tid >> 5] = s;
        __syncthreads();
        if (tid == 0) {
            float tot = 0.f;
#pragma unroll
            for (int w = 0; w < 8; w++) tot += warp_sums[w];
            g_y[row] = tot * (1.0f / ROW_ELEMS);
        }
        return;
    }

    // ------------- SCALE role: gate + scale half a row of group `step-1` -------------
    if (step < 1) return;

    // wait for the previous step's grid (its gap wrote g_y for group step-1)
    asm volatile("griddepcontrol.wait;" ::: "memory");

    const int row = (step - 1) * GROUP_ROWS + (bid >> 1);
    const int half = bid & 1;
    const int b = row / C;
    const int c = row % C;

    __shared__ float sh_y1[CS];
    __shared__ float sh_gate;
    {
        const int s_idx = tid >> 4;   // 0..15
        const int cc = tid & 15;      // 0..15
        const float* __restrict__ yb = g_y + b * C;
        const float* __restrict__ wrow = w1 + s_idx * C;
        float part = 0.f;
#pragma unroll
        for (int k = 0; k < C / 16; k++) {
            const int cidx = cc + k * 16;
            part += wrow[cidx] * yb[cidx];
        }
#pragma unroll
        for (int off = 8; off > 0; off >>= 1)
            part += __shfl_down_sync(0xFFFFFFFF, part, off, 16);
        if (cc == 0) {
            part += b1[s_idx];
            sh_y1[s_idx] = (part >= 0.f) ? part : NEG_SLOPE * part;
        }
    }
    __syncthreads();
    if (tid == 0) {
        const float* __restrict__ w2row = w2 + c * CS;
        float acc = b2[c];
#pragma unroll
        for (int s = 0; s < CS; s++) acc += w2row[s] * sh_y1[s];
        sh_gate = 1.0f / (1.0f + __expf(-acc));
    }
    __syncthreads();
    const float g = sh_gate;

    const size_t base_bytes =
        ((size_t)row * ROW_ELEMS + (size_t)half * (ROW_ELEMS / 2)) * 4;
    const char* __restrict__ xr = reinterpret_cast<const char*>(x) + base_bytes;
    char* __restrict__ orow = reinterpret_cast<char*>(out) + base_bytes;
#pragma unroll
    for (int i = 0; i < ROW_ELEMS / 2 / 8 / 256; i++) {   // 4 iters of 32B
        const size_t off = (size_t)(tid + i * 256) * 32;
        f8 v = ldg_32B(xr + off);   // mostly L2 hit: pinned by previous step's gap
        v.a0 *= g; v.a1 *= g; v.a2 *= g; v.a3 *= g;
        v.a4 *= g; v.a5 *= g; v.a6 *= g; v.a7 *= g;
        stg_evict_first_32B(orow + off, v);
    }
}

extern "C" void kernel_launch(void* const* d_in, const int* in_sizes, int n_in,
                              void* d_out, int out_size) {
    const float* x  = (const float*)d_in[0];
    const float* w1 = (const float*)d_in[1];
    const float* b1 = (const float*)d_in[2];
    const float* w2 = (const float*)d_in[3];
    const float* b2 = (const float*)d_in[4];
    float* out = (float*)d_out;

    cudaLaunchAttribute attr[1];
    attr[0].id = cudaLaunchAttributeProgrammaticStreamSerialization;
    attr[0].val.programmaticStreamSerializationAllowed = 1;

    cudaLaunchConfig_t cfg = {};
    cfg.gridDim = dim3(GRID, 1, 1);
    cfg.blockDim = dim3(256, 1, 1);
    cfg.dynamicSmemBytes = 0;
    cfg.stream = 0;
    cfg.attrs = attr;
    cfg.numAttrs = 1;

    // steps: 0 = gap(g0); 1..3 = scale(g-1)+gap(g); 4 = scale(g3)
    for (int step = 0; step <= NGROUPS; step++) {
        cudaLaunchKernelEx(&cfg, pipe_kernel, x, w1, b1, w2, b2, out, step);
    }
}